// round 2
// baseline (speedup 1.0000x reference)
#include <cuda_runtime.h>
#include <cooperative_groups.h>
#include <cstdint>

namespace cg = cooperative_groups;

// Problem constants
#define Bn   64
#define Tn   512
#define Dn   128
#define Hn   256
#define G4H  1024   // 4*H

// Precomputed input projections (val, mid, rad), layout [t][b][4H]
__device__ float g_pxv[(size_t)Tn * Bn * G4H];
__device__ float g_pxm[(size_t)Tn * Bn * G4H];
__device__ float g_pxr[(size_t)Tn * Bn * G4H];

// ---------------------------------------------------------------------------
// Phase 1: Px = x @ W_ih^T  (3 variants: v@W, m@W, r@|W|), bias folded into v,m
// Block tile: 32 rows (t*64+b) x 64 cols, K=128 full.
// ---------------------------------------------------------------------------
#define XS_PITCH 133
#define WS_PITCH 65

__global__ void __launch_bounds__(256) lstm_phase1(
    const float* __restrict__ xv, const float* __restrict__ xl,
    const float* __restrict__ xu, const float* __restrict__ Wih,
    const float* __restrict__ bias)
{
    extern __shared__ float sm1[];
    float* xsv = sm1;                       // [32][133]
    float* xsm = xsv + 32 * XS_PITCH;
    float* xsr = xsm + 32 * XS_PITCH;
    float* ws  = xsr + 32 * XS_PITCH;       // [128][65]  ws[d][col]

    const int tb0 = blockIdx.x * 32;        // row base (tb = t*64+b)
    const int t0  = tb0 >> 6;
    const int b0  = tb0 & 63;               // 32-aligned within 64 -> same t for whole block
    const int j0  = blockIdx.y * 64;        // col base
    const int tid = threadIdx.x;

    // Load x tile, convert to (v, m, r). Coalesced over d.
    for (int idx = tid; idx < 32 * 128; idx += 256) {
        int rr = idx >> 7, d = idx & 127;
        size_t a = ((size_t)(b0 + rr) * Tn + t0) * Dn + d;
        float v = xv[a], l = xl[a], u = xu[a];
        xsv[rr * XS_PITCH + d] = v;
        xsm[rr * XS_PITCH + d] = 0.5f * (l + u);
        xsr[rr * XS_PITCH + d] = 0.5f * (u - l);
    }
    // Load W tile transposed: ws[d][col]
    for (int idx = tid; idx < 64 * 128; idx += 256) {
        int cc = idx >> 7, d = idx & 127;
        ws[d * WS_PITCH + cc] = Wih[(size_t)(j0 + cc) * Dn + d];
    }
    __syncthreads();

    const int c = tid >> 5;     // warp -> column group (8 cols)
    const int r = tid & 31;     // lane -> row
    float av[8], am[8], ar[8];
#pragma unroll
    for (int q = 0; q < 8; q++) { av[q] = 0.f; am[q] = 0.f; ar[q] = 0.f; }

#pragma unroll 4
    for (int k = 0; k < 128; k++) {
        float xvv = xsv[r * XS_PITCH + k];
        float xmm = xsm[r * XS_PITCH + k];
        float xrr = xsr[r * XS_PITCH + k];
#pragma unroll
        for (int q = 0; q < 8; q++) {
            float w = ws[k * WS_PITCH + c * 8 + q];
            av[q] = fmaf(xvv, w, av[q]);
            am[q] = fmaf(xmm, w, am[q]);
            ar[q] = fmaf(xrr, fabsf(w), ar[q]);
        }
    }

    size_t ob = (size_t)(tb0 + r) * G4H + j0 + c * 8;
#pragma unroll
    for (int q = 0; q < 8; q++) {
        float bb = bias[j0 + c * 8 + q];
        g_pxv[ob + q] = av[q] + bb;
        g_pxm[ob + q] = am[q] + bb;
        g_pxr[ob + q] = ar[q];
    }
}

// ---------------------------------------------------------------------------
// Phase 2: recurrent interval-LSTM. Cluster of 8 CTAs = 4 batch rows, full H.
// Each CTA owns Hs=32 hidden units (all 4 gates -> 128 W_hh rows in SMEM).
// h triple (v,m,r) double-buffered in SMEM, broadcast via DSMEM push,
// one cluster.sync() per step.
// ---------------------------------------------------------------------------
#define WT_PITCH 132

struct I3 { float v, l, u; };

__device__ __forceinline__ float sigm(float x) {
    return 1.0f / (1.0f + __expf(-x));          // safe at both extremes
}
__device__ __forceinline__ float tanh_f(float x) {
    return 1.0f - 2.0f / (1.0f + __expf(2.0f * x)); // -> +-1, no inf/inf
}
__device__ __forceinline__ I3 imul(I3 a, I3 b) {
    float p1 = a.l * b.l, p2 = a.l * b.u, p3 = a.u * b.l, p4 = a.u * b.u;
    I3 o;
    o.v = a.v * b.v;
    o.l = fminf(fminf(p1, p2), fminf(p3, p4));
    o.u = fmaxf(fmaxf(p1, p2), fmaxf(p3, p4));
    return o;
}

__global__ void __cluster_dims__(8, 1, 1) __launch_bounds__(256)
lstm_phase2(const float* __restrict__ Whh, float* __restrict__ out)
{
    extern __shared__ float sm2[];
    float*  wt   = sm2;                                   // [256][132]  wt[k][col]
    float4* hbuf = (float4*)(wt + 256 * WT_PITCH);        // [2][4][256] (v,m,r,_)
    float4* gbuf = hbuf + 2 * 4 * 256;                    // [4][128]    (v,m,r,_)
    float4* cbuf = gbuf + 4 * 128;                        // [4][32]     (v,l,u,_)

    cg::cluster_group cluster = cg::this_cluster();
    const unsigned rank = cluster.block_rank();
    const int hbase = (int)rank * 32;
    const int bbase = (int)(blockIdx.x >> 3) * 4;
    const int tid = threadIdx.x;

    // Load W_hh slice, transposed: wt[k][col], col = g*32+j -> W row g*256+hbase+j
    for (int idx = tid; idx < 128 * 256; idx += 256) {
        int col = idx >> 8, k = idx & 255;
        int g = col >> 5, j = col & 31;
        wt[k * WT_PITCH + col] = Whh[(size_t)(g * 256 + hbase + j) * Hn + k];
    }
    // Zero hbuf[0] and c state
    for (int idx = tid; idx < 4 * 256; idx += 256)
        hbuf[idx] = make_float4(0.f, 0.f, 0.f, 0.f);
    if (tid < 128) cbuf[tid] = make_float4(0.f, 0.f, 0.f, 0.f);
    __syncthreads();
    cluster.sync();

    // GEMM mapping: 8 warps = 4 rows x 2 column halves; thread owns 2 cols.
    const int w    = tid >> 5;
    const int lane = tid & 31;
    const int row  = w & 3;
    const int half = w >> 2;
    const int col0 = half * 64 + lane * 2;

    // Elementwise mapping (tid < 128): one (row, j) cell
    const int erow = tid >> 5;   // 0..3 for tid<128
    const int ej   = tid & 31;

    const size_t PLANE = (size_t)Bn * Tn * Hn;

    for (int t = 0; t < Tn; t++) {
        const int cur = t & 1, nxt = cur ^ 1;

        // Prefetch Px for this step (independent of h -> issue before GEMM)
        float pv[4], pm[4], pr[4];
        if (tid < 128) {
            size_t base = ((size_t)t * 64 + bbase + erow) * G4H + hbase + ej;
#pragma unroll
            for (int g = 0; g < 4; g++) {
                pv[g] = g_pxv[base + g * 256];
                pm[g] = g_pxm[base + g * 256];
                pr[g] = g_pxr[base + g * 256];
            }
        }

        // Recurrent GEMM: acc(v,m,r) for 2 output cols over k=0..255
        float av0 = 0.f, am0 = 0.f, ar0 = 0.f;
        float av1 = 0.f, am1 = 0.f, ar1 = 0.f;
        const float4* hb = hbuf + cur * 4 * 256 + row * 256;
#pragma unroll 8
        for (int k = 0; k < 256; k++) {
            float4 h4 = hb[k];                                   // broadcast
            float2 w2 = *(const float2*)&wt[k * WT_PITCH + col0]; // conflict-free
            float a0 = fabsf(w2.x), a1 = fabsf(w2.y);
            av0 = fmaf(h4.x, w2.x, av0);
            am0 = fmaf(h4.y, w2.x, am0);
            ar0 = fmaf(h4.z, a0,   ar0);
            av1 = fmaf(h4.x, w2.y, av1);
            am1 = fmaf(h4.y, w2.y, am1);
            ar1 = fmaf(h4.z, a1,   ar1);
        }
        gbuf[row * 128 + col0]     = make_float4(av0, am0, ar0, 0.f);
        gbuf[row * 128 + col0 + 1] = make_float4(av1, am1, ar1, 0.f);
        __syncthreads();

        if (tid < 128) {
            I3 gate[4];
#pragma unroll
            for (int g = 0; g < 4; g++) {
                float4 acc = gbuf[erow * 128 + g * 32 + ej];
                float v = acc.x + pv[g];
                float m = acc.y + pm[g];
                float rr = acc.z + pr[g];
                gate[g].v = v; gate[g].l = m - rr; gate[g].u = m + rr;
            }
            I3 ig = { sigm(gate[0].v),   sigm(gate[0].l),   sigm(gate[0].u) };
            I3 fg = { sigm(gate[1].v),   sigm(gate[1].l),   sigm(gate[1].u) };
            I3 gg = { tanh_f(gate[2].v), tanh_f(gate[2].l), tanh_f(gate[2].u) };
            I3 og = { sigm(gate[3].v),   sigm(gate[3].l),   sigm(gate[3].u) };

            float4 c4 = cbuf[erow * 32 + ej];
            I3 cold = { c4.x, c4.y, c4.z };
            I3 fc  = imul(fg, cold);
            I3 igg = imul(ig, gg);
            I3 cn  = { fc.v + igg.v, fc.l + igg.l, fc.u + igg.u };
            I3 tc  = { tanh_f(cn.v), tanh_f(cn.l), tanh_f(cn.u) };
            I3 hn  = imul(og, tc);

            cbuf[erow * 32 + ej] = make_float4(cn.v, cn.l, cn.u, 0.f);

            // Global output: [3][B][T][H]
            size_t ob = (size_t)(bbase + erow) * Tn * Hn + (size_t)t * Hn + hbase + ej;
            out[ob]             = hn.v;
            out[ob + PLANE]     = hn.l;
            out[ob + 2 * PLANE] = hn.u;

            // Broadcast h_new (v, m, r) to every cluster CTA's next buffer
            float4 hout = make_float4(hn.v,
                                      0.5f * (hn.l + hn.u),
                                      0.5f * (hn.u - hn.l), 0.f);
            float4* dstbase = hbuf + nxt * 4 * 256 + erow * 256 + hbase + ej;
#pragma unroll
            for (unsigned p = 0; p < 8; p++) {
                float4* d = (float4*)cluster.map_shared_rank((void*)dstbase, p);
                *d = hout;
            }
        }
        cluster.sync();
    }
}

// ---------------------------------------------------------------------------
extern "C" void kernel_launch(void* const* d_in, const int* in_sizes, int n_in,
                              void* d_out, int out_size)
{
    const float* xv   = (const float*)d_in[0];
    const float* xl   = (const float*)d_in[1];
    const float* xu   = (const float*)d_in[2];
    const float* Wih  = (const float*)d_in[3];
    const float* Whh  = (const float*)d_in[4];
    const float* bias = (const float*)d_in[5];
    float* out = (float*)d_out;

    const int smem1 = (3 * 32 * XS_PITCH + 128 * WS_PITCH) * (int)sizeof(float);
    const int smem2 = (256 * WT_PITCH) * (int)sizeof(float)
                    + (2 * 4 * 256 + 4 * 128 + 4 * 32) * (int)sizeof(float4);

    cudaFuncSetAttribute(lstm_phase1, cudaFuncAttributeMaxDynamicSharedMemorySize, smem1);
    cudaFuncSetAttribute(lstm_phase2, cudaFuncAttributeMaxDynamicSharedMemorySize, smem2);

    // Phase 1: 32768 rows / 32 = 1024 blocks (x), 1024 cols / 64 = 16 blocks (y)
    lstm_phase1<<<dim3(1024, 16, 1), 256, smem1>>>(xv, xl, xu, Wih, bias);
    // Phase 2: 16 clusters x 8 CTAs, each cluster fully independent (4 batch rows)
    lstm_phase2<<<128, 256, smem2>>>(Whh, out);
}

// round 3
// speedup vs baseline: 1.0289x; 1.0289x over previous
#include <cuda_runtime.h>
#include <cooperative_groups.h>
#include <cstdint>

namespace cg = cooperative_groups;

#define Bn   64
#define Tn   512
#define Dn   128
#define Hn   256
#define G4H  1024

typedef unsigned long long ull;
#define AMASK 0x7FFFFFFF7FFFFFFFULL

__device__ float g_pxv[(size_t)Tn * Bn * G4H];
__device__ float g_pxm[(size_t)Tn * Bn * G4H];
__device__ float g_pxr[(size_t)Tn * Bn * G4H];

__device__ __forceinline__ ull pk2(float x) {
    ull r; asm("mov.b64 %0, {%1, %1};" : "=l"(r) : "f"(x)); return r;
}
__device__ __forceinline__ void fma2(ull& d, ull a, ull b) {
    asm("fma.rn.f32x2 %0, %1, %2, %0;" : "+l"(d) : "l"(a), "l"(b));
}
__device__ __forceinline__ float2 unp(ull v) {
    float2 f; asm("mov.b64 {%0, %1}, %2;" : "=f"(f.x), "=f"(f.y) : "l"(v)); return f;
}

// ---------------------------------------------------------------------------
// Phase 1: Px = x @ W_ih^T (v@W, m@W, r@|W|), bias folded into v,m.
// Block: 32 rows (fixed t, 32 consecutive b) x 128 cols, K=128.
// 8 warps = 8 row-groups; thread: R=4 rows x C=4 cols, packed f32x2.
// ---------------------------------------------------------------------------
#define WT1_PITCH 132

__global__ void __launch_bounds__(256, 1) lstm_phase1(
    const float* __restrict__ xv, const float* __restrict__ xl,
    const float* __restrict__ xu, const float* __restrict__ Wih,
    const float* __restrict__ bias)
{
    extern __shared__ float sm1[];
    float4* xs  = (float4*)sm1;                 // [32][128] (v, m, r, 0)
    float*  wt1 = (float*)(xs + 32 * 128);      // [128][132] w transposed

    const int tid  = threadIdx.x;
    const int lane = tid & 31;
    const int wp   = tid >> 5;
    const int tb0  = blockIdx.x * 32;
    const int t0   = tb0 >> 6;
    const int b0   = tb0 & 63;
    const int j0   = blockIdx.y * 128;

    // x tile -> (v, m, r)
    for (int idx = tid; idx < 32 * 128; idx += 256) {
        int rr = idx >> 7, d = idx & 127;
        size_t a = ((size_t)(b0 + rr) * Tn + t0) * Dn + d;
        float v = xv[a], l = xl[a], u = xu[a];
        xs[rr * 128 + d] = make_float4(v, 0.5f * (l + u), 0.5f * (u - l), 0.f);
    }
    // W tile transposed: wt1[k][c]; lanes = consecutive k -> conflict-free STS.128
#pragma unroll
    for (int i = 0; i < 4; i++) {
        int cq = wp + 8 * i;                    // col quad 0..31
#pragma unroll
        for (int j = 0; j < 4; j++) {
            int k = j * 32 + lane;
            float w0 = Wih[(size_t)(j0 + 4 * cq + 0) * Dn + k];
            float w1 = Wih[(size_t)(j0 + 4 * cq + 1) * Dn + k];
            float w2 = Wih[(size_t)(j0 + 4 * cq + 2) * Dn + k];
            float w3 = Wih[(size_t)(j0 + 4 * cq + 3) * Dn + k];
            *(float4*)&wt1[k * WT1_PITCH + 4 * cq] = make_float4(w0, w1, w2, w3);
        }
    }
    __syncthreads();

    const int r0 = wp * 4;
    const int c0 = lane * 4;
    ull A[4][6];
#pragma unroll
    for (int r = 0; r < 4; r++)
#pragma unroll
        for (int q = 0; q < 6; q++) A[r][q] = 0ULL;

#pragma unroll 4
    for (int k = 0; k < 128; k++) {
        ulonglong2 uw = *(ulonglong2*)&wt1[k * WT1_PITCH + c0];
        ull wa0 = uw.x & AMASK, wa1 = uw.y & AMASK;
#pragma unroll
        for (int r = 0; r < 4; r++) {
            float4 h = xs[(r0 + r) * 128 + k];
            ull vv = pk2(h.x), mm = pk2(h.y), rr = pk2(h.z);
            fma2(A[r][0], vv, uw.x); fma2(A[r][1], vv, uw.y);
            fma2(A[r][2], mm, uw.x); fma2(A[r][3], mm, uw.y);
            fma2(A[r][4], rr, wa0);  fma2(A[r][5], rr, wa1);
        }
    }

    float4 b4 = *(const float4*)&bias[j0 + c0];
#pragma unroll
    for (int r = 0; r < 4; r++) {
        size_t ob = (size_t)(tb0 + r0 + r) * G4H + j0 + c0;
        float2 v01 = unp(A[r][0]), v23 = unp(A[r][1]);
        float2 m01 = unp(A[r][2]), m23 = unp(A[r][3]);
        float2 q01 = unp(A[r][4]), q23 = unp(A[r][5]);
        *(float4*)&g_pxv[ob] = make_float4(v01.x + b4.x, v01.y + b4.y, v23.x + b4.z, v23.y + b4.w);
        *(float4*)&g_pxm[ob] = make_float4(m01.x + b4.x, m01.y + b4.y, m23.x + b4.z, m23.y + b4.w);
        *(float4*)&g_pxr[ob] = make_float4(q01.x, q01.y, q23.x, q23.y);
    }
}

// ---------------------------------------------------------------------------
// Phase 2: recurrent interval-LSTM. 16 clusters x 8 CTAs (4 batch rows each).
// CTA owns 32 hidden units (128 gate cols). 8 warps = 8 k-slices of 32.
// Thread: R=4 rows x C=4 cols, packed f32x2. h double-buffered via DSMEM push.
// ---------------------------------------------------------------------------
#define WT2_PITCH 132

struct I3 { float v, l, u; };

__device__ __forceinline__ float sigm(float x)   { return 1.0f / (1.0f + __expf(-x)); }
__device__ __forceinline__ float tanh_f(float x) { return 1.0f - 2.0f / (1.0f + __expf(2.0f * x)); }
__device__ __forceinline__ I3 imul(I3 a, I3 b) {
    float p1 = a.l * b.l, p2 = a.l * b.u, p3 = a.u * b.l, p4 = a.u * b.u;
    I3 o;
    o.v = a.v * b.v;
    o.l = fminf(fminf(p1, p2), fminf(p3, p4));
    o.u = fmaxf(fmaxf(p1, p2), fmaxf(p3, p4));
    return o;
}

__global__ void __cluster_dims__(8, 1, 1) __launch_bounds__(256, 1)
lstm_phase2(const float* __restrict__ Whh, float* __restrict__ out)
{
    extern __shared__ float sm2[];
    float*  wt   = sm2;                                   // [256][132]
    float4* hbuf = (float4*)(wt + 256 * WT2_PITCH);       // [2][4][256] (v,m,r,0)
    float4* gbuf = hbuf + 2 * 4 * 256;                    // [4 sets][4][128]

    cg::cluster_group cluster = cg::this_cluster();
    const unsigned rank  = cluster.block_rank();
    const int hbase = (int)rank * 32;
    const int bbase = (int)(blockIdx.x >> 3) * 4;
    const int tid  = threadIdx.x;
    const int lane = tid & 31;
    const int wp   = tid >> 5;

    // W_hh slice transposed: wt[k][c], c = g*32 + j; lanes = consecutive k.
#pragma unroll
    for (int i = 0; i < 4; i++) {
        int cq = wp + 8 * i;                    // col quad 0..31
#pragma unroll
        for (int j = 0; j < 8; j++) {
            int k = j * 32 + lane;
            float w[4];
#pragma unroll
            for (int q = 0; q < 4; q++) {
                int c = 4 * cq + q;
                int g = c >> 5, jj = c & 31;
                w[q] = Whh[(size_t)(g * 256 + hbase + jj) * Hn + k];
            }
            *(float4*)&wt[k * WT2_PITCH + 4 * cq] = make_float4(w[0], w[1], w[2], w[3]);
        }
    }
    for (int idx = tid; idx < 4 * 256; idx += 256)
        hbuf[idx] = make_float4(0.f, 0.f, 0.f, 0.f);
    __syncthreads();
    cluster.sync();

    const int kb   = wp * 32;
    const int c0   = lane * 4;
    const int erow = tid >> 5;      // tid<128: row
    const int ej   = tid & 31;      // tid<128: hidden j within slice
    float cv = 0.f, cl = 0.f, cu = 0.f;   // c state in registers

    const size_t PLANE = (size_t)Bn * Tn * Hn;

    for (int t = 0; t < Tn; t++) {
        const int cur = t & 1, nxt = cur ^ 1;

        // Px prefetch (independent of h; hides DRAM under GEMM)
        float pv[4], pm[4], pr[4];
        if (tid < 128) {
            size_t base = ((size_t)t * 64 + bbase + erow) * G4H + hbase + ej;
#pragma unroll
            for (int g = 0; g < 4; g++) {
                pv[g] = g_pxv[base + g * 256];
                pm[g] = g_pxm[base + g * 256];
                pr[g] = g_pxr[base + g * 256];
            }
        }

        // k-sliced GEMM
        ull A[4][6];
#pragma unroll
        for (int r = 0; r < 4; r++)
#pragma unroll
            for (int q = 0; q < 6; q++) A[r][q] = 0ULL;

        const float4* hb = hbuf + cur * 1024;
#pragma unroll 4
        for (int kk = 0; kk < 32; kk++) {
            int k = kb + kk;
            ulonglong2 uw = *(ulonglong2*)&wt[k * WT2_PITCH + c0];
            ull wa0 = uw.x & AMASK, wa1 = uw.y & AMASK;
#pragma unroll
            for (int r = 0; r < 4; r++) {
                float4 h = hb[r * 256 + k];
                ull vv = pk2(h.x), mm = pk2(h.y), rr = pk2(h.z);
                fma2(A[r][0], vv, uw.x); fma2(A[r][1], vv, uw.y);
                fma2(A[r][2], mm, uw.x); fma2(A[r][3], mm, uw.y);
                fma2(A[r][4], rr, wa0);  fma2(A[r][5], rr, wa1);
            }
        }

        // two-stage partial reduction over 8 k-slices -> 4 sets
        if (wp < 4) {
#pragma unroll
            for (int r = 0; r < 4; r++) {
                float2 v01 = unp(A[r][0]), v23 = unp(A[r][1]);
                float2 m01 = unp(A[r][2]), m23 = unp(A[r][3]);
                float2 q01 = unp(A[r][4]), q23 = unp(A[r][5]);
                float4* gp = gbuf + (wp * 4 + r) * 128 + c0;
                gp[0] = make_float4(v01.x, m01.x, q01.x, 0.f);
                gp[1] = make_float4(v01.y, m01.y, q01.y, 0.f);
                gp[2] = make_float4(v23.x, m23.x, q23.x, 0.f);
                gp[3] = make_float4(v23.y, m23.y, q23.y, 0.f);
            }
        }
        __syncthreads();
        if (wp >= 4) {
            int s = wp - 4;
#pragma unroll
            for (int r = 0; r < 4; r++) {
                float2 v01 = unp(A[r][0]), v23 = unp(A[r][1]);
                float2 m01 = unp(A[r][2]), m23 = unp(A[r][3]);
                float2 q01 = unp(A[r][4]), q23 = unp(A[r][5]);
                float4* gp = gbuf + (s * 4 + r) * 128 + c0;
                float4 g0 = gp[0], g1 = gp[1], g2 = gp[2], g3 = gp[3];
                g0.x += v01.x; g0.y += m01.x; g0.z += q01.x;
                g1.x += v01.y; g1.y += m01.y; g1.z += q01.y;
                g2.x += v23.x; g2.y += m23.x; g2.z += q23.x;
                g3.x += v23.y; g3.y += m23.y; g3.z += q23.y;
                gp[0] = g0; gp[1] = g1; gp[2] = g2; gp[3] = g3;
            }
        }
        __syncthreads();

        if (tid < 128) {
            I3 gate[4];
#pragma unroll
            for (int g = 0; g < 4; g++) {
                int col = g * 32 + ej;
                float v = pv[g], m = pm[g], rr = pr[g];
#pragma unroll
                for (int s = 0; s < 4; s++) {
                    float4 gs = gbuf[(s * 4 + erow) * 128 + col];
                    v += gs.x; m += gs.y; rr += gs.z;
                }
                gate[g].v = v; gate[g].l = m - rr; gate[g].u = m + rr;
            }
            I3 ig = { sigm(gate[0].v),   sigm(gate[0].l),   sigm(gate[0].u) };
            I3 fg = { sigm(gate[1].v),   sigm(gate[1].l),   sigm(gate[1].u) };
            I3 gg = { tanh_f(gate[2].v), tanh_f(gate[2].l), tanh_f(gate[2].u) };
            I3 og = { sigm(gate[3].v),   sigm(gate[3].l),   sigm(gate[3].u) };

            I3 cold = { cv, cl, cu };
            I3 fc  = imul(fg, cold);
            I3 igg = imul(ig, gg);
            I3 cn  = { fc.v + igg.v, fc.l + igg.l, fc.u + igg.u };
            I3 tc  = { tanh_f(cn.v), tanh_f(cn.l), tanh_f(cn.u) };
            I3 hn  = imul(og, tc);
            cv = cn.v; cl = cn.l; cu = cn.u;

            size_t ob = ((size_t)(bbase + erow) * Tn + t) * Hn + hbase + ej;
            out[ob]             = hn.v;
            out[ob + PLANE]     = hn.l;
            out[ob + 2 * PLANE] = hn.u;

            float4 hout = make_float4(hn.v, 0.5f * (hn.l + hn.u),
                                      0.5f * (hn.u - hn.l), 0.f);
            float4* dstl = hbuf + nxt * 1024 + erow * 256 + hbase + ej;
#pragma unroll
            for (unsigned p = 0; p < 8; p++) {
                float4* d = (float4*)cluster.map_shared_rank((void*)dstl, p);
                *d = hout;
            }
        }
        cluster.sync();
    }
}

// ---------------------------------------------------------------------------
extern "C" void kernel_launch(void* const* d_in, const int* in_sizes, int n_in,
                              void* d_out, int out_size)
{
    const float* xv   = (const float*)d_in[0];
    const float* xl   = (const float*)d_in[1];
    const float* xu   = (const float*)d_in[2];
    const float* Wih  = (const float*)d_in[3];
    const float* Whh  = (const float*)d_in[4];
    const float* bias = (const float*)d_in[5];
    float* out = (float*)d_out;

    const int smem1 = 32 * 128 * (int)sizeof(float4)
                    + 128 * WT1_PITCH * (int)sizeof(float);
    const int smem2 = 256 * WT2_PITCH * (int)sizeof(float)
                    + (2 * 4 * 256 + 4 * 4 * 128) * (int)sizeof(float4);

    cudaFuncSetAttribute(lstm_phase1, cudaFuncAttributeMaxDynamicSharedMemorySize, smem1);
    cudaFuncSetAttribute(lstm_phase2, cudaFuncAttributeMaxDynamicSharedMemorySize, smem2);

    // Phase 1: 1024 row-blocks (32 rows each) x 8 col-blocks (128 cols each)
    lstm_phase1<<<dim3(1024, 8, 1), 256, smem1>>>(xv, xl, xu, Wih, bias);
    // Phase 2: 16 clusters x 8 CTAs
    lstm_phase2<<<128, 256, smem2>>>(Whh, out);
}

// round 4
// speedup vs baseline: 1.5872x; 1.5425x over previous
#include <cuda_runtime.h>
#include <cstdint>

#define Bn   64
#define Tn   512
#define Dn   128
#define Hn   256
#define G4H  1024

typedef unsigned long long ull;
#define AMASK 0x7FFFFFFF7FFFFFFFULL

// Packed input projection: (v, m, r, _) per [t*64+b][4H]
__device__ float4 g_pxq[(size_t)Tn * Bn * G4H];
// h-slice staging through L2: [parity][group][cta][row*32+j] = (v, m, r, _)
__device__ float4 g_slice[2][16][8][128];
// step flags (zero-init; monotone per launch, replay-safe)
__device__ int g_flag[16][8];

__device__ __forceinline__ ull pk2(float x) {
    ull r; asm("mov.b64 %0, {%1, %1};" : "=l"(r) : "f"(x)); return r;
}
__device__ __forceinline__ void fma2(ull& d, ull a, ull b) {
    asm("fma.rn.f32x2 %0, %1, %2, %0;" : "+l"(d) : "l"(a), "l"(b));
}
__device__ __forceinline__ float2 unp(ull v) {
    float2 f; asm("mov.b64 {%0, %1}, %2;" : "=f"(f.x), "=f"(f.y) : "l"(v)); return f;
}
__device__ __forceinline__ int ld_acq(const int* p) {
    int v; asm volatile("ld.acquire.gpu.b32 %0, [%1];" : "=r"(v) : "l"(p) : "memory"); return v;
}
__device__ __forceinline__ void st_rel(int* p, int v) {
    asm volatile("st.release.gpu.b32 [%0], %1;" :: "l"(p), "r"(v) : "memory");
}
__device__ __forceinline__ float4 ldcg4(const float4* p) {
    float4 v;
    asm volatile("ld.global.cg.v4.f32 {%0,%1,%2,%3}, [%4];"
                 : "=f"(v.x), "=f"(v.y), "=f"(v.z), "=f"(v.w) : "l"(p));
    return v;
}

// ---------------------------------------------------------------------------
// Phase 1: Px = x @ W_ih^T (v@W, m@W, r@|W|), bias folded, packed float4 out.
// ---------------------------------------------------------------------------
#define WT1_PITCH 132

__global__ void __launch_bounds__(256, 1) lstm_phase1(
    const float* __restrict__ xv, const float* __restrict__ xl,
    const float* __restrict__ xu, const float* __restrict__ Wih,
    const float* __restrict__ bias)
{
    extern __shared__ float sm1[];
    float4* xs  = (float4*)sm1;                 // [32][128] (v, m, r, 0)
    float*  wt1 = (float*)(xs + 32 * 128);      // [128][132]

    const int tid  = threadIdx.x;
    const int lane = tid & 31;
    const int wp   = tid >> 5;
    const int tb0  = blockIdx.x * 32;
    const int t0   = tb0 >> 6;
    const int b0   = tb0 & 63;
    const int j0   = blockIdx.y * 128;

    for (int idx = tid; idx < 32 * 128; idx += 256) {
        int rr = idx >> 7, d = idx & 127;
        size_t a = ((size_t)(b0 + rr) * Tn + t0) * Dn + d;
        float v = xv[a], l = xl[a], u = xu[a];
        xs[rr * 128 + d] = make_float4(v, 0.5f * (l + u), 0.5f * (u - l), 0.f);
    }
#pragma unroll
    for (int i = 0; i < 4; i++) {
        int cq = wp + 8 * i;
#pragma unroll
        for (int j = 0; j < 4; j++) {
            int k = j * 32 + lane;
            float w0 = Wih[(size_t)(j0 + 4 * cq + 0) * Dn + k];
            float w1 = Wih[(size_t)(j0 + 4 * cq + 1) * Dn + k];
            float w2 = Wih[(size_t)(j0 + 4 * cq + 2) * Dn + k];
            float w3 = Wih[(size_t)(j0 + 4 * cq + 3) * Dn + k];
            *(float4*)&wt1[k * WT1_PITCH + 4 * cq] = make_float4(w0, w1, w2, w3);
        }
    }
    __syncthreads();

    const int r0 = wp * 4;
    const int c0 = lane * 4;
    ull A[4][6];
#pragma unroll
    for (int r = 0; r < 4; r++)
#pragma unroll
        for (int q = 0; q < 6; q++) A[r][q] = 0ULL;

#pragma unroll 4
    for (int k = 0; k < 128; k++) {
        ulonglong2 uw = *(ulonglong2*)&wt1[k * WT1_PITCH + c0];
        ull wa0 = uw.x & AMASK, wa1 = uw.y & AMASK;
#pragma unroll
        for (int r = 0; r < 4; r++) {
            float4 h = xs[(r0 + r) * 128 + k];
            ull vv = pk2(h.x), mm = pk2(h.y), rr = pk2(h.z);
            fma2(A[r][0], vv, uw.x); fma2(A[r][1], vv, uw.y);
            fma2(A[r][2], mm, uw.x); fma2(A[r][3], mm, uw.y);
            fma2(A[r][4], rr, wa0);  fma2(A[r][5], rr, wa1);
        }
    }

    float4 b4 = *(const float4*)&bias[j0 + c0];
#pragma unroll
    for (int r = 0; r < 4; r++) {
        size_t ob = (size_t)(tb0 + r0 + r) * G4H + j0 + c0;
        float2 v01 = unp(A[r][0]), v23 = unp(A[r][1]);
        float2 m01 = unp(A[r][2]), m23 = unp(A[r][3]);
        float2 q01 = unp(A[r][4]), q23 = unp(A[r][5]);
        g_pxq[ob + 0] = make_float4(v01.x + b4.x, m01.x + b4.x, q01.x, 0.f);
        g_pxq[ob + 1] = make_float4(v01.y + b4.y, m01.y + b4.y, q01.y, 0.f);
        g_pxq[ob + 2] = make_float4(v23.x + b4.z, m23.x + b4.z, q23.x, 0.f);
        g_pxq[ob + 3] = make_float4(v23.y + b4.w, m23.y + b4.w, q23.y, 0.f);
    }
}

// ---------------------------------------------------------------------------
// Phase 2: persistent recurrent interval-LSTM, NO clusters.
// 128 CTAs = 16 groups x 8 CTAs (one wave, co-resident). Group owns 4 batch
// rows; CTA owns 32 hidden units. h exchanged via L2 staging + release/acquire
// flags. 8 warps = 4 rows x 2 k-halves; thread: 1 row x 4 cols, f32x2 math.
// ---------------------------------------------------------------------------
#define WT2_PITCH 132

struct I3 { float v, l, u; };

__device__ __forceinline__ float sigm(float x)   { return 1.0f / (1.0f + __expf(-x)); }
__device__ __forceinline__ float tanh_f(float x) { return 1.0f - 2.0f / (1.0f + __expf(2.0f * x)); }
__device__ __forceinline__ I3 imul(I3 a, I3 b) {
    float p1 = a.l * b.l, p2 = a.l * b.u, p3 = a.u * b.l, p4 = a.u * b.u;
    I3 o;
    o.v = a.v * b.v;
    o.l = fminf(fminf(p1, p2), fminf(p3, p4));
    o.u = fmaxf(fmaxf(p1, p2), fmaxf(p3, p4));
    return o;
}

__global__ void __launch_bounds__(256, 1)
lstm_phase2(const float* __restrict__ Whh, float* __restrict__ out)
{
    extern __shared__ float sm2[];
    float* wt  = sm2;                               // [256][132]
    ull*   hv2 = (ull*)(wt + 256 * WT2_PITCH);      // [4][256] dup-packed v
    ull*   hm2 = hv2 + 4 * 256;                     // [4][256] dup-packed m
    ull*   hr2 = hm2 + 4 * 256;                     // [4][256] dup-packed r
    float4* gbuf = (float4*)(hr2 + 4 * 256);        // [2 khalf][4 row][128 col]

    const int tid  = threadIdx.x;
    const int lane = tid & 31;
    const int wp   = tid >> 5;
    const int grp  = blockIdx.x >> 3;   // 0..15 (4 batch rows each)
    const int cta  = blockIdx.x & 7;    // 0..7  (32 hidden units each)
    const int hbase = cta * 32;
    const int bbase = grp * 4;

    // W_hh slice transposed: wt[k][c], c = g*32 + j
#pragma unroll
    for (int i = 0; i < 4; i++) {
        int cq = wp + 8 * i;
#pragma unroll
        for (int j = 0; j < 8; j++) {
            int k = j * 32 + lane;
            float w[4];
#pragma unroll
            for (int q = 0; q < 4; q++) {
                int c = 4 * cq + q;
                int g = c >> 5, jj = c & 31;
                w[q] = Whh[(size_t)(g * 256 + hbase + jj) * Hn + k];
            }
            *(float4*)&wt[k * WT2_PITCH + 4 * cq] = make_float4(w[0], w[1], w[2], w[3]);
        }
    }
    for (int i = tid; i < 4 * 256; i += 256) { hv2[i] = 0ULL; hm2[i] = 0ULL; hr2[i] = 0ULL; }
    __syncthreads();

    const int row   = wp & 3;           // GEMM row
    const int khalf = wp >> 2;          // GEMM k-half
    const int c0    = lane * 4;
    const int erow  = tid >> 5;         // elementwise row (tid<128)
    const int ej    = tid & 31;         // elementwise j
    float cv = 0.f, cl = 0.f, cu = 0.f;

    const size_t PLANE = (size_t)Bn * Tn * Hn;

    for (int t = 0; t < Tn; t++) {
        // Px prefetch (independent of h)
        float4 P[4];
        if (tid < 128) {
            size_t base = ((size_t)t * 64 + bbase + erow) * G4H + hbase + ej;
#pragma unroll
            for (int g = 0; g < 4; g++) P[g] = g_pxq[base + g * 256];
        }

        if (t > 0) {
            // wait for all 8 slices of step t-1 (flag value t; peer may be at t+1)
            if (wp == 0 && lane < 8) {
                const int* fp = &g_flag[grp][lane];
                int v;
                do { v = ld_acq(fp); } while (v != t && v != t + 1);
            }
            __syncthreads();
            // pull full h(t-1): 8 slices x 128 float4 = 16KB from L2
            const float4* src = &g_slice[(t - 1) & 1][grp][0][0];
#pragma unroll
            for (int p = 0; p < 4; p++) {
                int idx = tid + p * 256;                  // 0..1023
                float4 s = ldcg4(src + idx);
                int k = ((idx >> 7) << 5) + (idx & 31);   // cta*32 + j
                int r = (idx >> 5) & 3;
                hv2[r * 256 + k] = pk2(s.x);
                hm2[r * 256 + k] = pk2(s.y);
                hr2[r * 256 + k] = pk2(s.z);
            }
            __syncthreads();
        }

        // GEMM: warp handles (row, khalf); thread 4 cols, 128 k
        ull A0 = 0, A1 = 0, A2 = 0, A3 = 0, A4 = 0, A5 = 0;
        const ull* hv = hv2 + row * 256 + khalf * 128;
        const ull* hm = hm2 + row * 256 + khalf * 128;
        const ull* hr = hr2 + row * 256 + khalf * 128;
        const float* wb = wt + (size_t)khalf * 128 * WT2_PITCH + c0;
#pragma unroll 8
        for (int kk = 0; kk < 128; kk++) {
            ulonglong2 w2 = *(const ulonglong2*)&wb[kk * WT2_PITCH];
            ull wa0 = w2.x & AMASK, wa1 = w2.y & AMASK;
            ull hvv = hv[kk], hmm = hm[kk], hrr = hr[kk];
            fma2(A0, hvv, w2.x); fma2(A1, hvv, w2.y);
            fma2(A2, hmm, w2.x); fma2(A3, hmm, w2.y);
            fma2(A4, hrr, wa0);  fma2(A5, hrr, wa1);
        }
        {
            float2 v01 = unp(A0), v23 = unp(A1);
            float2 m01 = unp(A2), m23 = unp(A3);
            float2 q01 = unp(A4), q23 = unp(A5);
            float4* gp = gbuf + (khalf * 4 + row) * 128 + c0;
            gp[0] = make_float4(v01.x, m01.x, q01.x, 0.f);
            gp[1] = make_float4(v01.y, m01.y, q01.y, 0.f);
            gp[2] = make_float4(v23.x, m23.x, q23.x, 0.f);
            gp[3] = make_float4(v23.y, m23.y, q23.y, 0.f);
        }
        __syncthreads();

        if (tid < 128) {
            I3 gate[4];
#pragma unroll
            for (int g = 0; g < 4; g++) {
                int col = g * 32 + ej;
                float4 a = gbuf[erow * 128 + col];
                float4 b = gbuf[(4 + erow) * 128 + col];
                float v  = a.x + b.x + P[g].x;
                float m  = a.y + b.y + P[g].y;
                float rr = a.z + b.z + P[g].z;
                gate[g].v = v; gate[g].l = m - rr; gate[g].u = m + rr;
            }
            I3 ig = { sigm(gate[0].v),   sigm(gate[0].l),   sigm(gate[0].u) };
            I3 fg = { sigm(gate[1].v),   sigm(gate[1].l),   sigm(gate[1].u) };
            I3 gg = { tanh_f(gate[2].v), tanh_f(gate[2].l), tanh_f(gate[2].u) };
            I3 og = { sigm(gate[3].v),   sigm(gate[3].l),   sigm(gate[3].u) };

            I3 cold = { cv, cl, cu };
            I3 fc  = imul(fg, cold);
            I3 igg = imul(ig, gg);
            I3 cn  = { fc.v + igg.v, fc.l + igg.l, fc.u + igg.u };
            I3 tc  = { tanh_f(cn.v), tanh_f(cn.l), tanh_f(cn.u) };
            I3 hn  = imul(og, tc);
            cv = cn.v; cl = cn.l; cu = cn.u;

            size_t ob = ((size_t)(bbase + erow) * Tn + t) * Hn + hbase + ej;
            out[ob]             = hn.v;
            out[ob + PLANE]     = hn.l;
            out[ob + 2 * PLANE] = hn.u;

            if (t < Tn - 1) {
                g_slice[t & 1][grp][cta][erow * 32 + ej] =
                    make_float4(hn.v, 0.5f * (hn.l + hn.u), 0.5f * (hn.u - hn.l), 0.f);
            }
        }
        if (t < Tn - 1) {
            __syncthreads();                     // all slice stores done
            if (tid == 0) st_rel(&g_flag[grp][cta], t + 1);
        }
    }
}

// ---------------------------------------------------------------------------
extern "C" void kernel_launch(void* const* d_in, const int* in_sizes, int n_in,
                              void* d_out, int out_size)
{
    const float* xv   = (const float*)d_in[0];
    const float* xl   = (const float*)d_in[1];
    const float* xu   = (const float*)d_in[2];
    const float* Wih  = (const float*)d_in[3];
    const float* Whh  = (const float*)d_in[4];
    const float* bias = (const float*)d_in[5];
    float* out = (float*)d_out;

    const int smem1 = 32 * 128 * (int)sizeof(float4)
                    + 128 * WT1_PITCH * (int)sizeof(float);
    const int smem2 = 256 * WT2_PITCH * (int)sizeof(float)
                    + 3 * 4 * 256 * (int)sizeof(ull)
                    + 2 * 4 * 128 * (int)sizeof(float4);

    cudaFuncSetAttribute(lstm_phase1, cudaFuncAttributeMaxDynamicSharedMemorySize, smem1);
    cudaFuncSetAttribute(lstm_phase2, cudaFuncAttributeMaxDynamicSharedMemorySize, smem2);

    lstm_phase1<<<dim3(1024, 8, 1), 256, smem1>>>(xv, xl, xu, Wih, bias);
    lstm_phase2<<<128, 256, smem2>>>(Whh, out);
}